// round 16
// baseline (speedup 1.0000x reference)
#include <cuda_runtime.h>
#include <cstdint>

// Problem constants
#define BB    8
#define FF    6
#define FM1   5          // frames used (1..5)
#define NBUF  5
#define NSLOT 7
#define HH    192
#define WW    192
#define CC    3
#define HW    (HH*WW)    // 36864

#define TPB   256
#define CHUNK_PX 256                        // pixels per block; 1 px per thread
#define CHUNKS_PER_IMG (HW/CHUNK_PX)        // 144
#define NIMG  (BB*FM1)                      // 40
#define GRID_MAIN (NIMG*CHUNKS_PER_IMG)     // 5760

// Ring SMEM: 25 slots of CHUNK_PX floats (1KB each) = 25.6KB
//   group 0: masks s -> slots 0..6,  seg n -> slots 7..11
//   group 1: vis  s -> slots 12..18, tgt c -> slots 19..21
//   group 2 (issued after Phase A): rec k=0..14 -> slot (k<12 ? k : 10+k+12... see REC_SLOT)
#define NSLOTS_SM 25
#define REC_SLOT(k) ((k) < 12 ? (k) : (10 + (k)))   // k=12,13,14 -> 22,23,24

#define EPSF   1e-7f
#define OMEPSF (1.0f - 1e-7f)

__device__ float g_partials[GRID_MAIN];
__device__ unsigned int g_ticket = 0;

__device__ __forceinline__ void cpa16(uint32_t saddr, const float* __restrict__ g) {
    asm volatile("cp.async.cg.shared.global [%0], [%1], 16;\n" :: "r"(saddr), "l"(g));
}

__global__ __launch_bounds__(TPB, 8)
void em_main(const float* __restrict__ seg,
             const float* __restrict__ masks,
             const float* __restrict__ rec,
             const float* __restrict__ tgt,
             const float* __restrict__ vis,
             const float* __restrict__ attn,
             float* __restrict__ out)
{
    __shared__ float sm_data[NSLOTS_SM * CHUNK_PX];        // 25.6 KB
    __shared__ __align__(16) float sAH_T[NBUF][8];         // attn*(1/HW), transposed [n][s], padded
    __shared__ __align__(16) float sAK_T[NBUF][8];         // attn*(0.1/C), transposed, padded
    __shared__ float sA[NBUF];                             // (1/HW)*sum_s attn[s][n]
    __shared__ float wsum[TPB / 32];
    __shared__ bool  isLast;

    const int tid   = (int)threadIdx.x;
    const int cid   = (int)blockIdx.x;
    const int img   = cid / CHUNKS_PER_IMG;
    const int chunk = cid % CHUNKS_PER_IMG;
    const int b = img / FM1;
    const int f = img % FM1 + 1;           // skip frame 0
    const int base = b*FF + f;
    const int pix0 = chunk * CHUNK_PX;

    const uint32_t smem0 = (uint32_t)__cvta_generic_to_shared(sm_data);
    const int q    = tid >> 6;             // 0..3: stream within a quad
    const int goff = (tid & 63) * 4;       // float offset of this 16B unit

    // ---------------- group 0: masks (7) + seg (5) = slots 0..11 ----------------
    #pragma unroll
    for (int s0 = 0; s0 < 12; s0 += 4) {
        int st = s0 + q;
        const float* gp = (st < NSLOT)
            ? masks + (size_t)(base*NSLOT + st)*HW + pix0 + goff
            : seg   + (size_t)(base*NBUF + (st-7))*HW + pix0 + goff;
        cpa16(smem0 + (uint32_t)(st*CHUNK_PX + goff)*4u, gp);
    }
    asm volatile("cp.async.commit_group;\n" ::: "memory");

    // ---------------- group 1: vis (7) + tgt (3) = slots 12..21 ----------------
    #pragma unroll
    for (int s0 = 0; s0 < 12; s0 += 4) {
        int st = s0 + q;
        if (st < 10) {
            const float* gp = (st < NSLOT)
                ? vis + (size_t)(base*NSLOT + st)*HW + pix0 + goff
                : tgt + (size_t)(base*CC + (st-7))*HW + pix0 + goff;
            cpa16(smem0 + (uint32_t)((12+st)*CHUNK_PX + goff)*4u, gp);
        }
    }
    asm volatile("cp.async.commit_group;\n" ::: "memory");

    // ---------------- attn coefficients (transposed + padded) ----------------
    const float invHW = 1.0f / (float)HW;
    const float Kc    = 0.1f / (float)CC;
    if (tid < NBUF * 8) {
        int n = tid >> 3, s = tid & 7;
        float a = (s < NSLOT) ? attn[(base*NSLOT + s)*NBUF + n] : 0.0f;
        sAH_T[n][s] = a * invHW;
        sAK_T[n][s] = a * Kc;
    }
    if (tid >= 64 && tid < 64 + NBUF) {
        int n = tid - 64;
        float sum = 0.0f;
        #pragma unroll
        for (int s = 0; s < NSLOT; s++)
            sum += attn[(base*NSLOT + s)*NBUF + n];
        sA[n] = sum * invHW;
    }

    #define SM(s) sm_data[(s)*CHUNK_PX + tid]

    float acc = 0.0f;

    // ================= Phase A: BCE (needs group 0) =================
    asm volatile("cp.async.wait_group 1;\n" ::: "memory");
    __syncthreads();   // group-0 data + coef tables visible

    {
        float tb[NSLOT];
        #pragma unroll
        for (int s = 0; s < NSLOT; s++)
            tb[s] = (SM(s) > 0.5f) ? 1.0f : 0.0f;

        #pragma unroll
        for (int n = 0; n < NBUF; n++) {
            float4 c0 = *reinterpret_cast<const float4*>(&sAH_T[n][0]);
            float4 c1 = *reinterpret_cast<const float4*>(&sAH_T[n][4]);
            float Tn = tb[0]*c0.x;
            Tn = fmaf(tb[1], c0.y, Tn);
            Tn = fmaf(tb[2], c0.z, Tn);
            Tn = fmaf(tb[3], c0.w, Tn);
            Tn = fmaf(tb[4], c1.x, Tn);
            Tn = fmaf(tb[5], c1.y, Tn);
            Tn = fmaf(tb[6], c1.z, Tn);

            float p   = SM(7+n);
            float An  = sA[n];
            float pc  = fminf(fmaxf(p, EPSF), OMEPSF);
            float lp  = __logf(pc);
            float l1m = __logf(1.0f - pc);     // == log1p(-p) in fp32 (Sterbenz)
            acc = fmaf(-Tn, lp, acc);
            acc = fmaf(Tn - An, l1m, acc);
        }
    }

    __syncthreads();   // all threads done reading slots 0..11

    // ---------------- group 2: rec (15) -> slots 0..11, 22..24 ----------------
    #pragma unroll
    for (int s0 = 0; s0 < 16; s0 += 4) {
        int st = s0 + q;
        if (st < NBUF*CC)
            cpa16(smem0 + (uint32_t)(REC_SLOT(st)*CHUNK_PX + goff)*4u,
                  rec + (size_t)(base*NBUF*CC + st)*HW + pix0 + goff);
    }
    asm volatile("cp.async.commit_group;\n" ::: "memory");

    // ================= Phase B: V + tgt (needs group 1) =================
    asm volatile("cp.async.wait_group 1;\n" ::: "memory");
    __syncthreads();

    float V[NBUF];
    {
        float vb[NSLOT];
        #pragma unroll
        for (int s = 0; s < NSLOT; s++)
            vb[s] = (SM(12+s) > 0.5f) ? 1.0f : 0.0f;

        #pragma unroll
        for (int n = 0; n < NBUF; n++) {
            float4 c0 = *reinterpret_cast<const float4*>(&sAK_T[n][0]);
            float4 c1 = *reinterpret_cast<const float4*>(&sAK_T[n][4]);
            float Vn = vb[0]*c0.x;
            Vn = fmaf(vb[1], c0.y, Vn);
            Vn = fmaf(vb[2], c0.z, Vn);
            Vn = fmaf(vb[3], c0.w, Vn);
            Vn = fmaf(vb[4], c1.x, Vn);
            Vn = fmaf(vb[5], c1.y, Vn);
            Vn = fmaf(vb[6], c1.z, Vn);
            V[n] = Vn;
        }
    }

    float tg[CC];
    #pragma unroll
    for (int c = 0; c < CC; c++) tg[c] = SM(19+c);

    // ================= Phase C: MSE (needs group 2) =================
    asm volatile("cp.async.wait_group 0;\n" ::: "memory");
    __syncthreads();

    #pragma unroll
    for (int n = 0; n < NBUF; n++) {
        float d2 = 0.0f;
        #pragma unroll
        for (int c = 0; c < CC; c++) {
            int k = n*CC + c;
            float dd = SM(REC_SLOT(k)) - tg[c];
            d2 = fmaf(dd, dd, d2);
        }
        acc = fmaf(V[n], d2, acc);
    }
    #undef SM

    // ================= block reduction =================
    float tot = acc;
    #pragma unroll
    for (int o = 16; o > 0; o >>= 1)
        tot += __shfl_down_sync(0xffffffffu, tot, o);

    if ((tid & 31) == 0) wsum[tid >> 5] = tot;
    __syncthreads();

    if (tid == 0) {
        float s = 0.0f;
        #pragma unroll
        for (int i = 0; i < TPB / 32; i++) s += wsum[i];
        g_partials[blockIdx.x] = s;
        __threadfence();
        unsigned prev = atomicAdd(&g_ticket, 1u);
        isLast = (prev == GRID_MAIN - 1);
    }
    __syncthreads();

    // ================= last block: final deterministic reduction =================
    if (isLast) {
        float v0 = 0.0f, v1 = 0.0f;
        #pragma unroll 1
        for (int i = tid; i < GRID_MAIN; i += TPB * 2) {
            v0 += g_partials[i];
            float x = (i + TPB < GRID_MAIN) ? g_partials[i + TPB] : 0.0f;
            v1 += x;
        }
        float v = v0 + v1;
        #pragma unroll
        for (int o = 16; o > 0; o >>= 1)
            v += __shfl_down_sync(0xffffffffu, v, o);
        if ((tid & 31) == 0) wsum[tid >> 5] = v;
        __syncthreads();
        if (tid == 0) {
            float s = 0.0f;
            #pragma unroll
            for (int i = 0; i < TPB / 32; i++) s += wsum[i];
            // total / (B*(F-1)*NB*NS) * LOSS_WEIGHT = total * 20/1400
            out[0] = s * (20.0f / 1400.0f);
            atomicExch(&g_ticket, 0u);          // reset for next graph replay
        }
    }
}

extern "C" void kernel_launch(void* const* d_in, const int* in_sizes, int n_in,
                              void* d_out, int out_size)
{
    const float* seg   = (const float*)d_in[0];  // segmentations   [B,F,NB,H,W]
    const float* masks = (const float*)d_in[1];  // masks           [B,F,NS,H,W]
    const float* rec   = (const float*)d_in[2];  // reconstructions [B,F,NB,C,H,W]
    const float* tgt   = (const float*)d_in[3];  // rec_tgt         [B,F,C,H,W]
    const float* vis   = (const float*)d_in[4];  // masks_vis       [B,F,NS,H,W]
    const float* attn  = (const float*)d_in[5];  // attn_index      [B,F,NS,NB]
    (void)in_sizes; (void)n_in; (void)out_size;

    em_main<<<GRID_MAIN, TPB>>>(seg, masks, rec, tgt, vis, attn, (float*)d_out);
}